// round 1
// baseline (speedup 1.0000x reference)
#include <cuda_runtime.h>
#include <math.h>

// Problem constants
#define Bc   8
#define Sc   512
#define Dc   1024
#define Hc   16
#define DHc  64
#define Mc   1024
#define DFc  4096
#define Vc   32000
#define Lc   6

// ---------------------------------------------------------------------------
// Scratch (device globals: allocation-free per harness rules)
// ---------------------------------------------------------------------------
__device__ float g_x[Bc * Sc * Dc];        // running activations  [4096,1024]
__device__ float g_q[Bc * Sc * Dc];        // Q projection
__device__ float g_k[Bc * Mc * Dc];        // K projection (max 8192 rows for cross)
__device__ float g_v[Bc * Mc * Dc];        // V projection
__device__ float g_a[Bc * Sc * Dc];        // attention output
__device__ float g_o[Bc * Sc * Dc];        // post-projection / FFN2 output
__device__ float g_f[Bc * Sc * DFc];       // FFN hidden [4096,4096]

// ---------------------------------------------------------------------------
// SGEMM: C[M,N] = A[M,K] @ B[K,N]  (+bias, +relu, optional B^T i.e. B is [N,K])
// 128x128 tile, BK=16, 256 threads, 8x8 microtile. All dims divide exactly.
// ---------------------------------------------------------------------------
template <bool TRANSB, bool BIAS, bool RELU>
__global__ void __launch_bounds__(256)
sgemm_kernel(const float* __restrict__ A, const float* __restrict__ B,
             const float* __restrict__ bias, float* __restrict__ C,
             int M, int N, int K)
{
    __shared__ float As[16 * 128];   // transposed: As[k][m]
    __shared__ float Bs[16 * 128];   // Bs[k][n]

    const int tid = threadIdx.x;
    const int tx  = tid & 15;        // n direction (16)
    const int ty  = tid >> 4;        // m direction (16)
    const int m0  = blockIdx.y * 128;
    const int n0  = blockIdx.x * 128;

    float acc[8][8];
#pragma unroll
    for (int i = 0; i < 8; i++)
#pragma unroll
        for (int j = 0; j < 8; j++) acc[i][j] = 0.f;

    for (int k0 = 0; k0 < K; k0 += 16) {
        // ---- load A tile 128x16 (transposed into smem) ----
#pragma unroll
        for (int s = tid; s < 512; s += 256) {
            int row = s >> 2;
            int c4  = s & 3;
            float4 v = *reinterpret_cast<const float4*>(
                A + (size_t)(m0 + row) * K + k0 + c4 * 4);
            As[(c4 * 4 + 0) * 128 + row] = v.x;
            As[(c4 * 4 + 1) * 128 + row] = v.y;
            As[(c4 * 4 + 2) * 128 + row] = v.z;
            As[(c4 * 4 + 3) * 128 + row] = v.w;
        }
        // ---- load B tile 16x128 ----
        if (!TRANSB) {
#pragma unroll
            for (int s = tid; s < 512; s += 256) {
                int kr = s >> 5;
                int n4 = s & 31;
                float4 v = *reinterpret_cast<const float4*>(
                    B + (size_t)(k0 + kr) * N + n0 + n4 * 4);
                *reinterpret_cast<float4*>(&Bs[kr * 128 + n4 * 4]) = v;
            }
        } else {
            // B is [N, K]; need Bs[k][n] = B[n*K + k]
#pragma unroll
            for (int s = tid; s < 512; s += 256) {
                int n  = s >> 2;
                int c4 = s & 3;
                float4 v = *reinterpret_cast<const float4*>(
                    B + (size_t)(n0 + n) * K + k0 + c4 * 4);
                Bs[(c4 * 4 + 0) * 128 + n] = v.x;
                Bs[(c4 * 4 + 1) * 128 + n] = v.y;
                Bs[(c4 * 4 + 2) * 128 + n] = v.z;
                Bs[(c4 * 4 + 3) * 128 + n] = v.w;
            }
        }
        __syncthreads();

#pragma unroll
        for (int k = 0; k < 16; k++) {
            float a[8], b[8];
            *reinterpret_cast<float4*>(a)     = *reinterpret_cast<float4*>(&As[k * 128 + ty * 8]);
            *reinterpret_cast<float4*>(a + 4) = *reinterpret_cast<float4*>(&As[k * 128 + ty * 8 + 4]);
            *reinterpret_cast<float4*>(b)     = *reinterpret_cast<float4*>(&Bs[k * 128 + tx * 8]);
            *reinterpret_cast<float4*>(b + 4) = *reinterpret_cast<float4*>(&Bs[k * 128 + tx * 8 + 4]);
#pragma unroll
            for (int i = 0; i < 8; i++)
#pragma unroll
                for (int j = 0; j < 8; j++)
                    acc[i][j] += a[i] * b[j];
        }
        __syncthreads();
    }

    // ---- epilogue ----
    float bv[8];
    if (BIAS) {
#pragma unroll
        for (int j = 0; j < 8; j++) bv[j] = bias[n0 + tx * 8 + j];
    }
#pragma unroll
    for (int i = 0; i < 8; i++) {
        size_t crow = (size_t)(m0 + ty * 8 + i) * N + n0 + tx * 8;
#pragma unroll
        for (int j = 0; j < 8; j += 4) {
            float4 v;
            float e0 = acc[i][j + 0], e1 = acc[i][j + 1], e2 = acc[i][j + 2], e3 = acc[i][j + 3];
            if (BIAS) { e0 += bv[j]; e1 += bv[j + 1]; e2 += bv[j + 2]; e3 += bv[j + 3]; }
            if (RELU) {
                e0 = fmaxf(e0, 0.f); e1 = fmaxf(e1, 0.f);
                e2 = fmaxf(e2, 0.f); e3 = fmaxf(e3, 0.f);
            }
            v.x = e0; v.y = e1; v.z = e2; v.w = e3;
            *reinterpret_cast<float4*>(C + crow + j) = v;
        }
    }
}

// ---------------------------------------------------------------------------
// Fused attention (flash-style online softmax), fp32.
// Q: [B, Sq=512, H, 64], K/V: [B, Lk, H, 64], O: [B, Sq, H, 64] (all as [.,1024])
// Block: 32 q rows, 128 threads (4 warps x 8 rows). K tiles of 32.
// ---------------------------------------------------------------------------
template <bool CAUSAL>
__global__ void __launch_bounds__(128)
attn_kernel(const float* __restrict__ Q, const float* __restrict__ K,
            const float* __restrict__ V, float* __restrict__ O, int Lk)
{
    __shared__ float Qs[32 * 64];     // [r][d]
    __shared__ float Kst[64 * 33];    // transposed [d][k], pad 33 (conflict-free)
    __shared__ float Vs[32 * 68];     // [k][c], pad 68 (16B-aligned rows)
    __shared__ float Ps[32 * 32];     // probs [r][k] (per-warp slices)

    const int b    = blockIdx.z;
    const int h    = blockIdx.y;
    const int q0   = blockIdx.x * 32;
    const int tid  = threadIdx.x;
    const int lane = tid & 31;
    const int w    = tid >> 5;
    const int r0   = w * 8;

    // load Q tile (32 x 64)
#pragma unroll
    for (int s = tid; s < 512; s += 128) {
        int r  = s >> 4;
        int c4 = s & 15;
        float4 v = *reinterpret_cast<const float4*>(
            Q + (size_t)(b * Sc + q0 + r) * Dc + h * 64 + c4 * 4);
        *reinterpret_cast<float4*>(&Qs[r * 64 + c4 * 4]) = v;
    }

    float m_run[8], l_run[8], o0[8], o1[8];
#pragma unroll
    for (int r = 0; r < 8; r++) { m_run[r] = -1e30f; l_run[r] = 0.f; o0[r] = 0.f; o1[r] = 0.f; }

    const int nkt = CAUSAL ? (blockIdx.x + 1) : (Lk >> 5);

    for (int kt = 0; kt < nkt; kt++) {
        const int k0 = kt * 32;
        __syncthreads();   // guards Qs on first iter, Vs reuse on later iters
        // load K tile (transposed) + V tile
#pragma unroll
        for (int s = tid; s < 512; s += 128) {
            int r  = s >> 4;
            int c4 = s & 15;
            size_t base = (size_t)(b * Lk + k0 + r) * Dc + h * 64 + c4 * 4;
            float4 kv = *reinterpret_cast<const float4*>(K + base);
            Kst[(c4 * 4 + 0) * 33 + r] = kv.x;
            Kst[(c4 * 4 + 1) * 33 + r] = kv.y;
            Kst[(c4 * 4 + 2) * 33 + r] = kv.z;
            Kst[(c4 * 4 + 3) * 33 + r] = kv.w;
            float4 vv = *reinterpret_cast<const float4*>(V + base);
            *reinterpret_cast<float4*>(&Vs[r * 68 + c4 * 4]) = vv;
        }
        __syncthreads();

        // scores: lane owns key k0+lane for this warp's 8 q rows
        float sc[8];
#pragma unroll
        for (int r = 0; r < 8; r++) sc[r] = 0.f;
#pragma unroll 4
        for (int d = 0; d < 64; d++) {
            float kv = Kst[d * 33 + lane];
#pragma unroll
            for (int r = 0; r < 8; r++)
                sc[r] += Qs[(r0 + r) * 64 + d] * kv;
        }
#pragma unroll
        for (int r = 0; r < 8; r++) {
            sc[r] *= 0.125f;                       // 1/sqrt(64)
            if (CAUSAL) {
                int qg = q0 + r0 + r;
                int kg = k0 + lane;
                if (kg > qg) sc[r] = -1e9f;        // matches reference mask fill
            }
        }
        // online softmax per row
#pragma unroll
        for (int r = 0; r < 8; r++) {
            float mx = sc[r];
#pragma unroll
            for (int off = 16; off > 0; off >>= 1)
                mx = fmaxf(mx, __shfl_xor_sync(0xffffffffu, mx, off));
            float m_new = fmaxf(m_run[r], mx);
            float p = expf(sc[r] - m_new);
            float ps = p;
#pragma unroll
            for (int off = 16; off > 0; off >>= 1)
                ps += __shfl_xor_sync(0xffffffffu, ps, off);
            float alpha = expf(m_run[r] - m_new);
            l_run[r] = l_run[r] * alpha + ps;
            m_run[r] = m_new;
            o0[r] *= alpha;
            o1[r] *= alpha;
            Ps[(r0 + r) * 32 + lane] = p;
        }
        __syncwarp();
        // PV: lane owns output cols c0=lane, c1=lane+32
#pragma unroll 8
        for (int k = 0; k < 32; k++) {
            float v0 = Vs[k * 68 + lane];
            float v1 = Vs[k * 68 + 32 + lane];
#pragma unroll
            for (int r = 0; r < 8; r++) {
                float p = Ps[(r0 + r) * 32 + k];
                o0[r] += p * v0;
                o1[r] += p * v1;
            }
        }
    }

#pragma unroll
    for (int r = 0; r < 8; r++) {
        float invl = 1.f / l_run[r];
        float* op = O + (size_t)(b * Sc + q0 + r0 + r) * Dc + h * 64;
        op[lane]      = o0[r] * invl;
        op[32 + lane] = o1[r] * invl;
    }
}

// ---------------------------------------------------------------------------
// Residual + LayerNorm: out = LN(x + add) * s + b   (add == nullptr -> LN(x))
// One block per row (D=1024), 256 threads x 4 elems.
// ---------------------------------------------------------------------------
__global__ void __launch_bounds__(256)
ln_kernel(const float* __restrict__ x, const float* __restrict__ add,
          const float* __restrict__ s, const float* __restrict__ b,
          float* __restrict__ out)
{
    const int row = blockIdx.x;
    const int tid = threadIdx.x;
    const size_t base = (size_t)row * Dc;

    float v[4];
    float sum = 0.f, sq = 0.f;
#pragma unroll
    for (int i = 0; i < 4; i++) {
        int c = tid + i * 256;
        float val = x[base + c];
        if (add) val += add[base + c];
        v[i] = val;
        sum += val;
        sq  += val * val;
    }
    // block reduce (sum, sq)
#pragma unroll
    for (int off = 16; off > 0; off >>= 1) {
        sum += __shfl_xor_sync(0xffffffffu, sum, off);
        sq  += __shfl_xor_sync(0xffffffffu, sq, off);
    }
    __shared__ float s1[8], s2[8];
    __shared__ float mu_s, inv_s;
    int lane = tid & 31, wid = tid >> 5;
    if (lane == 0) { s1[wid] = sum; s2[wid] = sq; }
    __syncthreads();
    if (tid == 0) {
        float ts = 0.f, tq = 0.f;
#pragma unroll
        for (int i = 0; i < 8; i++) { ts += s1[i]; tq += s2[i]; }
        float mu  = ts * (1.f / Dc);
        float var = tq * (1.f / Dc) - mu * mu;
        mu_s  = mu;
        inv_s = rsqrtf(var + 1e-5f);
    }
    __syncthreads();
    float mu = mu_s, inv = inv_s;
#pragma unroll
    for (int i = 0; i < 4; i++) {
        int c = tid + i * 256;
        out[base + c] = (v[i] - mu) * inv * s[c] + b[c];
    }
}

// ---------------------------------------------------------------------------
// Embedding gather + positional add
// ---------------------------------------------------------------------------
__global__ void __launch_bounds__(256)
embed_kernel(const int* __restrict__ seq, const float* __restrict__ emb,
             const float* __restrict__ pos, float* __restrict__ x)
{
    const int row  = blockIdx.x;            // b*S + s
    const int sidx = row & (Sc - 1);        // S = 512
    const int tok  = seq[row];
    const int tid  = threadIdx.x;
#pragma unroll
    for (int i = 0; i < 4; i++) {
        int c = tid + i * 256;
        x[(size_t)row * Dc + c] = emb[(size_t)tok * Dc + c] + pos[(size_t)sidx * Dc + c];
    }
}

// ---------------------------------------------------------------------------
// Host orchestration
// ---------------------------------------------------------------------------
template <bool TRANSB, bool BIAS, bool RELU>
static void launch_gemm(const float* A, const float* B, const float* bias,
                        float* C, int M, int N, int K)
{
    dim3 grid(N / 128, M / 128);
    sgemm_kernel<TRANSB, BIAS, RELU><<<grid, 256>>>(A, B, bias, C, M, N, K);
}

extern "C" void kernel_launch(void* const* d_in, const int* in_sizes, int n_in,
                              void* d_out, int out_size)
{
    (void)in_sizes; (void)n_in; (void)out_size;

    const float* encoded      = (const float*)d_in[0];
    const int*   seq          = (const int*)  d_in[1];
    const float* input_embed  = (const float*)d_in[2];
    const float* output_embed = (const float*)d_in[3];
    const float* output_bias  = (const float*)d_in[4];
    const float* pos_embed    = (const float*)d_in[5];
    const float* Wq  = (const float*)d_in[6];
    const float* Wk  = (const float*)d_in[7];
    const float* Wv  = (const float*)d_in[8];
    const float* Wo  = (const float*)d_in[9];
    const float* Wqc = (const float*)d_in[10];
    const float* Wkc = (const float*)d_in[11];
    const float* Wvc = (const float*)d_in[12];
    const float* Woc = (const float*)d_in[13];
    const float* W1  = (const float*)d_in[14];
    const float* b1  = (const float*)d_in[15];
    const float* W2  = (const float*)d_in[16];
    const float* b2  = (const float*)d_in[17];
    const float* ln1s = (const float*)d_in[18];
    const float* ln1b = (const float*)d_in[19];
    const float* ln2s = (const float*)d_in[20];
    const float* ln2b = (const float*)d_in[21];
    const float* ln3s = (const float*)d_in[22];
    const float* ln3b = (const float*)d_in[23];
    const float* lnfs = (const float*)d_in[24];
    const float* lnfb = (const float*)d_in[25];

    float *x, *q, *k, *v, *a, *o, *f;
    cudaGetSymbolAddress((void**)&x, g_x);
    cudaGetSymbolAddress((void**)&q, g_q);
    cudaGetSymbolAddress((void**)&k, g_k);
    cudaGetSymbolAddress((void**)&v, g_v);
    cudaGetSymbolAddress((void**)&a, g_a);
    cudaGetSymbolAddress((void**)&o, g_o);
    cudaGetSymbolAddress((void**)&f, g_f);

    const int NR  = Bc * Sc;   // 4096 decoder rows
    const int NRE = Bc * Mc;   // 8192 encoder rows

    embed_kernel<<<NR, 256>>>(seq, input_embed, pos_embed, x);

    const dim3 agrid(Sc / 32, Hc, Bc);   // (16, 16, 8)

    for (int i = 0; i < Lc; i++) {
        const size_t wo = (size_t)i * Dc * Dc;

        // ---- self attention ----
        launch_gemm<false, false, false>(x, Wq + wo, nullptr, q, NR, Dc, Dc);
        launch_gemm<false, false, false>(x, Wk + wo, nullptr, k, NR, Dc, Dc);
        launch_gemm<false, false, false>(x, Wv + wo, nullptr, v, NR, Dc, Dc);
        attn_kernel<true><<<agrid, 128>>>(q, k, v, a, Sc);
        launch_gemm<false, false, false>(a, Wo + wo, nullptr, o, NR, Dc, Dc);
        ln_kernel<<<NR, 256>>>(x, o, ln1s + (size_t)i * Dc, ln1b + (size_t)i * Dc, x);

        // ---- cross attention ----
        launch_gemm<false, false, false>(x,       Wqc + wo, nullptr, q, NR,  Dc, Dc);
        launch_gemm<false, false, false>(encoded, Wkc + wo, nullptr, k, NRE, Dc, Dc);
        launch_gemm<false, false, false>(encoded, Wvc + wo, nullptr, v, NRE, Dc, Dc);
        attn_kernel<false><<<agrid, 128>>>(q, k, v, a, Mc);
        launch_gemm<false, false, false>(a, Woc + wo, nullptr, o, NR, Dc, Dc);
        ln_kernel<<<NR, 256>>>(x, o, ln2s + (size_t)i * Dc, ln2b + (size_t)i * Dc, x);

        // ---- FFN ----
        launch_gemm<false, true, true >(x, W1 + (size_t)i * Dc * DFc, b1 + (size_t)i * DFc,
                                        f, NR, DFc, Dc);
        launch_gemm<false, true, false>(f, W2 + (size_t)i * DFc * Dc, b2 + (size_t)i * Dc,
                                        o, NR, Dc, DFc);
        ln_kernel<<<NR, 256>>>(x, o, ln3s + (size_t)i * Dc, ln3b + (size_t)i * Dc, x);
    }

    // final norm + logits: out = LN(x) @ E^T + bias
    ln_kernel<<<NR, 256>>>(x, nullptr, lnfs, lnfb, x);
    launch_gemm<true, true, false>(x, output_embed, output_bias, (float*)d_out, NR, Vc, Dc);
}

// round 3
// speedup vs baseline: 1.8683x; 1.8683x over previous
#include <cuda_runtime.h>
#include <cuda_bf16.h>
#include <math.h>
#include <stdint.h>

// Problem constants
#define Bc   8
#define Sc   512
#define Dc   1024
#define Hc   16
#define DHc  64
#define Mc   1024
#define DFc  4096
#define Vc   32000
#define Lc   6

// ---------------------------------------------------------------------------
// Scratch (device globals: allocation-free per harness rules)
// ---------------------------------------------------------------------------
__device__ float g_x[Bc * Sc * Dc];
__device__ float g_q[Bc * Sc * Dc];
__device__ float g_k[Bc * Mc * Dc];
__device__ float g_v[Bc * Mc * Dc];
__device__ float g_a[Bc * Sc * Dc];
__device__ float g_o[Bc * Sc * Dc];
__device__ float g_f[Bc * Sc * DFc];

// ===========================================================================
// bf16 hi/lo split helper: x ~= hi + lo with |x-hi-lo| <~ 2^-16 |x|
// ===========================================================================
__device__ __forceinline__ void split2(float x, float y, uint32_t& hi, uint32_t& lo) {
    __nv_bfloat162 h = __floats2bfloat162_rn(x, y);
    float rx = x - __low2float(h);
    float ry = y - __high2float(h);
    __nv_bfloat162 l = __floats2bfloat162_rn(rx, ry);
    hi = *reinterpret_cast<uint32_t*>(&h);
    lo = *reinterpret_cast<uint32_t*>(&l);
}

// mma.sync m16n8k16 row.col f32.bf16.bf16.f32
__device__ __forceinline__ void mma_bf16(float* d, const uint32_t* a, const uint32_t* b) {
    asm volatile(
        "mma.sync.aligned.m16n8k16.row.col.f32.bf16.bf16.f32 "
        "{%0,%1,%2,%3}, {%4,%5,%6,%7}, {%8,%9}, {%0,%1,%2,%3};"
        : "+f"(d[0]), "+f"(d[1]), "+f"(d[2]), "+f"(d[3])
        : "r"(a[0]), "r"(a[1]), "r"(a[2]), "r"(a[3]), "r"(b[0]), "r"(b[1]));
}

// ===========================================================================
// Tensor-core GEMM via mma.sync (bf16 3-pass hi/lo split, fp32 accum)
//   C[M,N] = A[M,K] @ B  (+bias, +relu)
//   B_KMAJOR=false: B is [K,N] row-major (weights)
//   B_KMAJOR=true : B is [N,K] row-major (logits: output_embed)
// 128x128 CTA tile, BK=32, 256 threads (8 warps, 2x4), warp tile 64x32.
// Smem tiles k-major, pitch 40 bf16 (conflict-free frag loads), double buffer.
// ===========================================================================
#define BKg   32
#define PITCH 40                         // bf16 elems per smem row (32 used)
#define TILEB (128 * PITCH * 2)          // 10240 bytes per tile
#define STAGEB (4 * TILEB)               // Ahi, Alo, Bhi, Blo = 40960
#define GEMM_SMEM (2 * STAGEB)           // 81920 (>= 128*132*4 epilogue stage)

template <bool B_KMAJOR, bool BIAS, bool RELU>
__global__ void __launch_bounds__(256, 1)
tc_gemm(const float* __restrict__ A, const float* __restrict__ B,
        const float* __restrict__ bias, float* __restrict__ C,
        int M, int N, int K)
{
    extern __shared__ char smem[];
    const int tid  = threadIdx.x;
    const int wid  = tid >> 5;
    const int lane = tid & 31;
    const int g    = lane >> 2;      // 0..7
    const int t    = lane & 3;       // 0..3
    const int wm   = wid & 1;        // 2 m-groups of 64
    const int wn   = wid >> 1;       // 4 n-groups of 32
    const int m0   = blockIdx.y * 128;
    const int n0   = blockIdx.x * 128;

    // LDG staging registers
    const int arow = tid >> 3;        // 0..31 (x4 iters -> 128 rows)
    const int ac4  = tid & 7;         // float4 index within 32-col row
    const int bn   = tid & 127;       // !B_KMAJOR: n within tile
    const int bkh  = tid >> 7;        // !B_KMAJOR: k-half (0/1)

    float4 aR[4];
    float4 bR4[4];                    // B_KMAJOR path
    float  bRs[16];                   // !B_KMAJOR path

    float acc[4][4][4];
#pragma unroll
    for (int i = 0; i < 4; i++)
#pragma unroll
        for (int j = 0; j < 4; j++)
#pragma unroll
            for (int c = 0; c < 4; c++) acc[i][j][c] = 0.f;

    const int S = K >> 5;

    // ---- LDG helpers (inlined) ----
    auto ldg_stage = [&](int s) {
        const int k0 = s << 5;
#pragma unroll
        for (int i = 0; i < 4; i++) {
            int row = arow + i * 32;
            aR[i] = *reinterpret_cast<const float4*>(
                A + (size_t)(m0 + row) * K + k0 + ac4 * 4);
        }
        if (B_KMAJOR) {
#pragma unroll
            for (int i = 0; i < 4; i++) {
                int row = arow + i * 32;
                bR4[i] = *reinterpret_cast<const float4*>(
                    B + (size_t)(n0 + row) * K + k0 + ac4 * 4);
            }
        } else {
#pragma unroll
            for (int j = 0; j < 4; j++) {
                int kl = bkh * 16 + j * 4;
                const float* bp = B + (size_t)(k0 + kl) * N + n0 + bn;
                bRs[j * 4 + 0] = bp[0];
                bRs[j * 4 + 1] = bp[(size_t)N];
                bRs[j * 4 + 2] = bp[(size_t)2 * N];
                bRs[j * 4 + 3] = bp[(size_t)3 * N];
            }
        }
    };

    auto sts_stage = [&](int b) {
        char* buf = smem + b * STAGEB;
        char* Ahi = buf;
        char* Alo = buf + TILEB;
        char* Bhi = buf + 2 * TILEB;
        char* Blo = buf + 3 * TILEB;
#pragma unroll
        for (int i = 0; i < 4; i++) {
            int row = arow + i * 32;
            uint32_t h0, l0, h1, l1;
            split2(aR[i].x, aR[i].y, h0, l0);
            split2(aR[i].z, aR[i].w, h1, l1);
            uint32_t byte = (uint32_t)(row * (PITCH * 2) + ac4 * 8);
            uint64_t hv = ((uint64_t)h1 << 32) | h0;
            uint64_t lv = ((uint64_t)l1 << 32) | l0;
            *reinterpret_cast<uint64_t*>(Ahi + byte) = hv;
            *reinterpret_cast<uint64_t*>(Alo + byte) = lv;
        }
        if (B_KMAJOR) {
#pragma unroll
            for (int i = 0; i < 4; i++) {
                int row = arow + i * 32;
                uint32_t h0, l0, h1, l1;
                split2(bR4[i].x, bR4[i].y, h0, l0);
                split2(bR4[i].z, bR4[i].w, h1, l1);
                uint32_t byte = (uint32_t)(row * (PITCH * 2) + ac4 * 8);
                uint64_t hv = ((uint64_t)h1 << 32) | h0;
                uint64_t lv = ((uint64_t)l1 << 32) | l0;
                *reinterpret_cast<uint64_t*>(Bhi + byte) = hv;
                *reinterpret_cast<uint64_t*>(Blo + byte) = lv;
            }
        } else {
#pragma unroll
            for (int j = 0; j < 4; j++) {
                int kl = bkh * 16 + j * 4;
                uint32_t h0, l0, h1, l1;
                split2(bRs[j * 4 + 0], bRs[j * 4 + 1], h0, l0);
                split2(bRs[j * 4 + 2], bRs[j * 4 + 3], h1, l1);
                uint32_t byte = (uint32_t)(bn * (PITCH * 2) + kl * 2);
                uint64_t hv = ((uint64_t)h1 << 32) | h0;
                uint64_t lv = ((uint64_t)l1 << 32) | l0;
                *reinterpret_cast<uint64_t*>(Bhi + byte) = hv;
                *reinterpret_cast<uint64_t*>(Blo + byte) = lv;
            }
        }
    };

    auto compute_stage = [&](int b) {
        const __nv_bfloat16* Ah = reinterpret_cast<const __nv_bfloat16*>(smem + b * STAGEB);
        const __nv_bfloat16* Al = Ah + 128 * PITCH;
        const __nv_bfloat16* Bh = Al + 128 * PITCH;
        const __nv_bfloat16* Bl = Bh + 128 * PITCH;
#pragma unroll
        for (int ks = 0; ks < 2; ks++) {
            const int kb = ks * 16 + t * 2;
            uint32_t ah[4][4], bh[4][2], bl[4][2], al[4][4];
#pragma unroll
            for (int mt = 0; mt < 4; mt++) {
                const __nv_bfloat16* p = Ah + (wm * 64 + mt * 16 + g) * PITCH + kb;
                ah[mt][0] = *reinterpret_cast<const uint32_t*>(p);
                ah[mt][1] = *reinterpret_cast<const uint32_t*>(p + 8 * PITCH);
                ah[mt][2] = *reinterpret_cast<const uint32_t*>(p + 8);
                ah[mt][3] = *reinterpret_cast<const uint32_t*>(p + 8 * PITCH + 8);
            }
#pragma unroll
            for (int nt = 0; nt < 4; nt++) {
                const __nv_bfloat16* p = Bh + (wn * 32 + nt * 8 + g) * PITCH + kb;
                bh[nt][0] = *reinterpret_cast<const uint32_t*>(p);
                bh[nt][1] = *reinterpret_cast<const uint32_t*>(p + 8);
            }
#pragma unroll
            for (int mt = 0; mt < 4; mt++)
#pragma unroll
                for (int nt = 0; nt < 4; nt++)
                    mma_bf16(acc[mt][nt], ah[mt], bh[nt]);
#pragma unroll
            for (int nt = 0; nt < 4; nt++) {
                const __nv_bfloat16* p = Bl + (wn * 32 + nt * 8 + g) * PITCH + kb;
                bl[nt][0] = *reinterpret_cast<const uint32_t*>(p);
                bl[nt][1] = *reinterpret_cast<const uint32_t*>(p + 8);
            }
#pragma unroll
            for (int mt = 0; mt < 4; mt++)
#pragma unroll
                for (int nt = 0; nt < 4; nt++)
                    mma_bf16(acc[mt][nt], ah[mt], bl[nt]);
#pragma unroll
            for (int mt = 0; mt < 4; mt++) {
                const __nv_bfloat16* p = Al + (wm * 64 + mt * 16 + g) * PITCH + kb;
                al[mt][0] = *reinterpret_cast<const uint32_t*>(p);
                al[mt][1] = *reinterpret_cast<const uint32_t*>(p + 8 * PITCH);
                al[mt][2] = *reinterpret_cast<const uint32_t*>(p + 8);
                al[mt][3] = *reinterpret_cast<const uint32_t*>(p + 8 * PITCH + 8);
            }
#pragma unroll
            for (int mt = 0; mt < 4; mt++)
#pragma unroll
                for (int nt = 0; nt < 4; nt++)
                    mma_bf16(acc[mt][nt], al[mt], bh[nt]);
        }
    };

    // ---- software pipeline ----
    ldg_stage(0);
    sts_stage(0);
    __syncthreads();

    for (int s = 0; s < S; s++) {
        if (s + 1 < S) ldg_stage(s + 1);
        compute_stage(s & 1);
        if (s + 1 < S) sts_stage((s + 1) & 1);
        __syncthreads();
    }

    // ---- epilogue: regs -> smem stage -> coalesced global (+bias/relu) ----
    float* stage = reinterpret_cast<float*>(smem);   // 128 x pitch 132
#pragma unroll
    for (int mt = 0; mt < 4; mt++) {
#pragma unroll
        for (int nt = 0; nt < 4; nt++) {
            int row = wm * 64 + mt * 16 + g;
            int col = wn * 32 + nt * 8 + t * 2;
            *reinterpret_cast<float2*>(&stage[row * 132 + col]) =
                make_float2(acc[mt][nt][0], acc[mt][nt][1]);
            *reinterpret_cast<float2*>(&stage[(row + 8) * 132 + col]) =
                make_float2(acc[mt][nt][2], acc[mt][nt][3]);
        }
    }
    __syncthreads();

#pragma unroll
    for (int i = 0; i < 16; i++) {
        int f   = i * 256 + tid;
        int row = f >> 5;
        int c4  = f & 31;
        float4 v = *reinterpret_cast<float4*>(&stage[row * 132 + c4 * 4]);
        if (BIAS) {
            float4 bv = *reinterpret_cast<const float4*>(bias + n0 + c4 * 4);
            v.x += bv.x; v.y += bv.y; v.z += bv.z; v.w += bv.w;
        }
        if (RELU) {
            v.x = fmaxf(v.x, 0.f); v.y = fmaxf(v.y, 0.f);
            v.z = fmaxf(v.z, 0.f); v.w = fmaxf(v.w, 0.f);
        }
        *reinterpret_cast<float4*>(C + (size_t)(m0 + row) * N + n0 + c4 * 4) = v;
    }
}

// ---------------------------------------------------------------------------
// Fused attention (flash-style online softmax), fp32. (R1-proven)
// ---------------------------------------------------------------------------
template <bool CAUSAL>
__global__ void __launch_bounds__(128)
attn_kernel(const float* __restrict__ Q, const float* __restrict__ K,
            const float* __restrict__ V, float* __restrict__ O, int Lk)
{
    __shared__ float Qs[32 * 64];
    __shared__ float Kst[64 * 33];
    __shared__ float Vs[32 * 68];
    __shared__ float Ps[32 * 32];

    const int b    = blockIdx.z;
    const int h    = blockIdx.y;
    const int q0   = blockIdx.x * 32;
    const int tid  = threadIdx.x;
    const int lane = tid & 31;
    const int w    = tid >> 5;
    const int r0   = w * 8;

#pragma unroll
    for (int s = tid; s < 512; s += 128) {
        int r  = s >> 4;
        int c4 = s & 15;
        float4 v = *reinterpret_cast<const float4*>(
            Q + (size_t)(b * Sc + q0 + r) * Dc + h * 64 + c4 * 4);
        *reinterpret_cast<float4*>(&Qs[r * 64 + c4 * 4]) = v;
    }

    float m_run[8], l_run[8], o0[8], o1[8];
#pragma unroll
    for (int r = 0; r < 8; r++) { m_run[r] = -1e30f; l_run[r] = 0.f; o0[r] = 0.f; o1[r] = 0.f; }

    const int nkt = CAUSAL ? (blockIdx.x + 1) : (Lk >> 5);

    for (int kt = 0; kt < nkt; kt++) {
        const int k0 = kt * 32;
        __syncthreads();
#pragma unroll
        for (int s = tid; s < 512; s += 128) {
            int r  = s >> 4;
            int c4 = s & 15;
            size_t base = (size_t)(b * Lk + k0 + r) * Dc + h * 64 + c4 * 4;
            float4 kv = *reinterpret_cast<const float4*>(K + base);
            Kst[(c4 * 4 + 0) * 33 + r] = kv.x;
            Kst[(c4 * 4 + 1) * 33 + r] = kv.y;
            Kst[(c4 * 4 + 2) * 33 + r] = kv.z;
            Kst[(c4 * 4 + 3) * 33 + r] = kv.w;
            float4 vv = *reinterpret_cast<const float4*>(V + base);
            *reinterpret_cast<float4*>(&Vs[r * 68 + c4 * 4]) = vv;
        }
        __syncthreads();

        float sc[8];
#pragma unroll
        for (int r = 0; r < 8; r++) sc[r] = 0.f;
#pragma unroll 4
        for (int d = 0; d < 64; d++) {
            float kv = Kst[d * 33 + lane];
#pragma unroll
            for (int r = 0; r < 8; r++)
                sc[r] += Qs[(r0 + r) * 64 + d] * kv;
        }
#pragma unroll
        for (int r = 0; r < 8; r++) {
            sc[r] *= 0.125f;
            if (CAUSAL) {
                int qg = q0 + r0 + r;
                int kg = k0 + lane;
                if (kg > qg) sc[r] = -1e9f;
            }
        }
#pragma unroll
        for (int r = 0; r < 8; r++) {
            float mx = sc[r];
#pragma unroll
            for (int off = 16; off > 0; off >>= 1)
                mx = fmaxf(mx, __shfl_xor_sync(0xffffffffu, mx, off));
            float m_new = fmaxf(m_run[r], mx);
            float p = expf(sc[r] - m_new);
            float ps = p;
#pragma unroll
            for (int off = 16; off > 0; off >>= 1)
                ps += __shfl_xor_sync(0xffffffffu, ps, off);
            float alpha = expf(m_run[r] - m_new);
            l_run[r] = l_run[r] * alpha + ps;
            m_run[r] = m_new;
            o0[r] *= alpha;
            o1[r] *= alpha;
            Ps[(r0 + r) * 32 + lane] = p;
        }
        __syncwarp();
#pragma unroll 8
        for (int k = 0; k < 32; k++) {
            float v0 = Vs[k * 68 + lane];
            float v1 = Vs[k * 68 + 32 + lane];
#pragma unroll
            for (int r = 0; r < 8; r++) {
                float p = Ps[(r0 + r) * 32 + k];
                o0[r] += p * v0;
                o1[r] += p * v1;
            }
        }
    }

#pragma unroll
    for (int r = 0; r < 8; r++) {
        float invl = 1.f / l_run[r];
        float* op = O + (size_t)(b * Sc + q0 + r0 + r) * Dc + h * 64;
        op[lane]      = o0[r] * invl;
        op[32 + lane] = o1[r] * invl;
    }
}

// ---------------------------------------------------------------------------
// Residual + LayerNorm
// ---------------------------------------------------------------------------
__global__ void __launch_bounds__(256)
ln_kernel(const float* __restrict__ x, const float* __restrict__ add,
          const float* __restrict__ s, const float* __restrict__ b,
          float* __restrict__ out)
{
    const int row = blockIdx.x;
    const int tid = threadIdx.x;
    const size_t base = (size_t)row * Dc;

    float v[4];
    float sum = 0.f, sq = 0.f;
#pragma unroll
    for (int i = 0; i < 4; i++) {
        int c = tid + i * 256;
        float val = x[base + c];
        if (add) val += add[base + c];
        v[i] = val;
        sum += val;
        sq  += val * val;
    }
#pragma unroll
    for (int off = 16; off > 0; off >>= 1) {
        sum += __shfl_xor_sync(0xffffffffu, sum, off);
        sq  += __shfl_xor_sync(0xffffffffu, sq, off);
    }
    __shared__ float s1[8], s2[8];
    __shared__ float mu_s, inv_s;
    int lane = tid & 31, wid = tid >> 5;
    if (lane == 0) { s1[wid] = sum; s2[wid] = sq; }
    __syncthreads();
    if (tid == 0) {
        float ts = 0.f, tq = 0.f;
#pragma unroll
        for (int i = 0; i < 8; i++) { ts += s1[i]; tq += s2[i]; }
        float mu  = ts * (1.f / Dc);
        float var = tq * (1.f / Dc) - mu * mu;
        mu_s  = mu;
        inv_s = rsqrtf(var + 1e-5f);
    }
    __syncthreads();
    float mu = mu_s, inv = inv_s;
#pragma unroll
    for (int i = 0; i < 4; i++) {
        int c = tid + i * 256;
        out[base + c] = (v[i] - mu) * inv * s[c] + b[c];
    }
}

// ---------------------------------------------------------------------------
// Embedding gather + positional add
// ---------------------------------------------------------------------------
__global__ void __launch_bounds__(256)
embed_kernel(const int* __restrict__ seq, const float* __restrict__ emb,
             const float* __restrict__ pos, float* __restrict__ x)
{
    const int row  = blockIdx.x;
    const int sidx = row & (Sc - 1);
    const int tok  = seq[row];
    const int tid  = threadIdx.x;
#pragma unroll
    for (int i = 0; i < 4; i++) {
        int c = tid + i * 256;
        x[(size_t)row * Dc + c] = emb[(size_t)tok * Dc + c] + pos[(size_t)sidx * Dc + c];
    }
}

// ---------------------------------------------------------------------------
// Host orchestration
// ---------------------------------------------------------------------------
template <bool B_KMAJOR, bool BIAS, bool RELU>
static void launch_gemm(const float* A, const float* B, const float* bias,
                        float* C, int M, int N, int K)
{
    cudaFuncSetAttribute(tc_gemm<B_KMAJOR, BIAS, RELU>,
                         cudaFuncAttributeMaxDynamicSharedMemorySize, GEMM_SMEM);
    dim3 grid(N / 128, M / 128);
    tc_gemm<B_KMAJOR, BIAS, RELU><<<grid, 256, GEMM_SMEM>>>(A, B, bias, C, M, N, K);
}

extern "C" void kernel_launch(void* const* d_in, const int* in_sizes, int n_in,
                              void* d_out, int out_size)
{
    (void)in_sizes; (void)n_in; (void)out_size;

    const float* encoded      = (const float*)d_in[0];
    const int*   seq          = (const int*)  d_in[1];
    const float* input_embed  = (const float*)d_in[2];
    const float* output_embed = (const float*)d_in[3];
    const float* output_bias  = (const float*)d_in[4];
    const float* pos_embed    = (const float*)d_in[5];
    const float* Wq  = (const float*)d_in[6];
    const float* Wk  = (const float*)d_in[7];
    const float* Wv  = (const float*)d_in[8];
    const float* Wo  = (const float*)d_in[9];
    const float* Wqc = (const float*)d_in[10];
    const float* Wkc = (const float*)d_in[11];
    const float* Wvc = (const float*)d_in[12];
    const float* Woc = (const float*)d_in[13];
    const float* W1  = (const float*)d_in[14];
    const float* b1  = (const float*)d_in[15];
    const float* W2  = (const float*)d_in[16];
    const float* b2  = (const float*)d_in[17];
    const float* ln1s = (const float*)d_in[18];
    const float* ln1b = (const float*)d_in[19];
    const float* ln2s = (const float*)d_in[20];
    const float* ln2b = (const float*)d_in[21];
    const float* ln3s = (const float*)d_in[22];
    const float* ln3b = (const float*)d_in[23];
    const float* lnfs = (const float*)d_in[24];
    const float* lnfb = (const float*)d_in[25];

    float *x, *q, *k, *v, *a, *o, *f;
    cudaGetSymbolAddress((void**)&x, g_x);
    cudaGetSymbolAddress((void**)&q, g_q);
    cudaGetSymbolAddress((void**)&k, g_k);
    cudaGetSymbolAddress((void**)&v, g_v);
    cudaGetSymbolAddress((void**)&a, g_a);
    cudaGetSymbolAddress((void**)&o, g_o);
    cudaGetSymbolAddress((void**)&f, g_f);

    const int NR  = Bc * Sc;   // 4096 decoder rows
    const int NRE = Bc * Mc;   // 8192 encoder rows

    embed_kernel<<<NR, 256>>>(seq, input_embed, pos_embed, x);

    const dim3 agrid(Sc / 32, Hc, Bc);   // (16, 16, 8)

    for (int i = 0; i < Lc; i++) {
        const size_t wo = (size_t)i * Dc * Dc;

        // ---- self attention ----
        launch_gemm<false, false, false>(x, Wq + wo, nullptr, q, NR, Dc, Dc);
        launch_gemm<false, false, false>(x, Wk + wo, nullptr, k, NR, Dc, Dc);
        launch_gemm<false, false, false>(x, Wv + wo, nullptr, v, NR, Dc, Dc);
        attn_kernel<true><<<agrid, 128>>>(q, k, v, a, Sc);
        launch_gemm<false, false, false>(a, Wo + wo, nullptr, o, NR, Dc, Dc);
        ln_kernel<<<NR, 256>>>(x, o, ln1s + (size_t)i * Dc, ln1b + (size_t)i * Dc, x);

        // ---- cross attention ----
        launch_gemm<false, false, false>(x,       Wqc + wo, nullptr, q, NR,  Dc, Dc);
        launch_gemm<false, false, false>(encoded, Wkc + wo, nullptr, k, NRE, Dc, Dc);
        launch_gemm<false, false, false>(encoded, Wvc + wo, nullptr, v, NRE, Dc, Dc);
        attn_kernel<false><<<agrid, 128>>>(q, k, v, a, Mc);
        launch_gemm<false, false, false>(a, Woc + wo, nullptr, o, NR, Dc, Dc);
        ln_kernel<<<NR, 256>>>(x, o, ln2s + (size_t)i * Dc, ln2b + (size_t)i * Dc, x);

        // ---- FFN ----
        launch_gemm<false, true, true >(x, W1 + (size_t)i * Dc * DFc, b1 + (size_t)i * DFc,
                                        f, NR, DFc, Dc);
        launch_gemm<false, true, false>(f, W2 + (size_t)i * DFc * Dc, b2 + (size_t)i * Dc,
                                        o, NR, Dc, DFc);
        ln_kernel<<<NR, 256>>>(x, o, ln3s + (size_t)i * Dc, ln3b + (size_t)i * Dc, x);
    }

    // final norm + logits: out = LN(x) @ E^T + bias
    ln_kernel<<<NR, 256>>>(x, nullptr, lnfs, lnfb, x);
    launch_gemm<true, true, false>(x, output_embed, output_bias, (float*)d_out, NR, Vc, Dc);
}

// round 4
// speedup vs baseline: 1.9932x; 1.0668x over previous
#include <cuda_runtime.h>
#include <cuda_bf16.h>
#include <math.h>
#include <stdint.h>

// Problem constants
#define Bc   8
#define Sc   512
#define Dc   1024
#define Hc   16
#define DHc  64
#define Mc   1024
#define DFc  4096
#define Vc   32000
#define Lc   6

// ---------------------------------------------------------------------------
// Scratch (device globals: allocation-free per harness rules)
// ---------------------------------------------------------------------------
__device__ float g_x[Bc * Sc * Dc];
__device__ float g_q[Bc * Sc * Dc];
__device__ float g_k[Bc * Mc * Dc];
__device__ float g_v[Bc * Mc * Dc];
__device__ float g_a[Bc * Sc * Dc];
__device__ float g_o[Bc * Sc * Dc];
__device__ float g_f[Bc * Sc * DFc];

// Pre-converted weights: [N,K] bf16 hi/lo.
// Per layer: Wq,Wk,Wv,Wo,Wqc,Wkc,Wvc,Woc (1M each), W1^T (4M), W2^T (4M) = 16M
// Total: 6*16M + output_embed 32.768M-elem = 133,431,296 elems per buffer.
#define WOFF_LAYER 16777216ull
#define WOFF_W1    8388608ull
#define WOFF_W2    12582912ull
#define EOFF       100663296ull
#define WTOTAL     133431296ull
__device__ __nv_bfloat16 g_whi[WTOTAL];
__device__ __nv_bfloat16 g_wlo[WTOTAL];

// ===========================================================================
// helpers
// ===========================================================================
__device__ __forceinline__ uint32_t smem_u32(const void* p) {
    uint32_t a;
    asm("{ .reg .u64 t; cvta.to.shared.u64 t, %1; cvt.u32.u64 %0, t; }"
        : "=r"(a) : "l"(p));
    return a;
}

__device__ __forceinline__ void split2(float x, float y, uint32_t& hi, uint32_t& lo) {
    __nv_bfloat162 h = __floats2bfloat162_rn(x, y);
    float rx = x - __low2float(h);
    float ry = y - __high2float(h);
    __nv_bfloat162 l = __floats2bfloat162_rn(rx, ry);
    hi = *reinterpret_cast<uint32_t*>(&h);
    lo = *reinterpret_cast<uint32_t*>(&l);
}

__device__ __forceinline__ void mma_bf16(float* d, const uint32_t* a, const uint32_t* b) {
    asm volatile(
        "mma.sync.aligned.m16n8k16.row.col.f32.bf16.bf16.f32 "
        "{%0,%1,%2,%3}, {%4,%5,%6,%7}, {%8,%9}, {%0,%1,%2,%3};"
        : "+f"(d[0]), "+f"(d[1]), "+f"(d[2]), "+f"(d[3])
        : "r"(a[0]), "r"(a[1]), "r"(a[2]), "r"(a[3]), "r"(b[0]), "r"(b[1]));
}

#define CP_ASYNC16(dst, src) \
    asm volatile("cp.async.cg.shared.global [%0], [%1], 16;" :: "r"(dst), "l"(src))
#define CP_COMMIT()  asm volatile("cp.async.commit_group;" ::: "memory")
#define CP_WAIT0()   asm volatile("cp.async.wait_group 0;" ::: "memory")

// ===========================================================================
// Weight conversion kernels (run once per launch; part of graph)
// ===========================================================================
// Transpose-convert: W [K,N] fp32 -> hi/lo [N,K] bf16. Block (32,8), tile 32x32.
__global__ void convT_kernel(const float* __restrict__ W,
                             __nv_bfloat16* __restrict__ hi,
                             __nv_bfloat16* __restrict__ lo, int K, int N)
{
    __shared__ float ts[32][33];
    const int k0 = blockIdx.y * 32, n0 = blockIdx.x * 32;
    const int tx = threadIdx.x, ty = threadIdx.y;
#pragma unroll
    for (int j = 0; j < 4; j++)
        ts[ty + j * 8][tx] = W[(size_t)(k0 + ty + j * 8) * N + n0 + tx];
    __syncthreads();
#pragma unroll
    for (int j = 0; j < 4; j++) {
        int n = ty + j * 8;
        float v = ts[tx][n];
        __nv_bfloat16 h = __float2bfloat16(v);
        float r = v - __bfloat162float(h);
        size_t o = (size_t)(n0 + n) * K + k0 + tx;
        hi[o] = h;
        lo[o] = __float2bfloat16(r);
    }
}

// Straight conversion (already [N,K]): float4 per thread.
__global__ void conv_kernel(const float4* __restrict__ src,
                            __nv_bfloat162* __restrict__ hi,
                            __nv_bfloat162* __restrict__ lo)
{
    size_t i = (size_t)blockIdx.x * blockDim.x + threadIdx.x;
    float4 v = src[i];
    __nv_bfloat162 h0 = __floats2bfloat162_rn(v.x, v.y);
    __nv_bfloat162 h1 = __floats2bfloat162_rn(v.z, v.w);
    float rx = v.x - __low2float(h0), ry = v.y - __high2float(h0);
    float rz = v.z - __low2float(h1), rw = v.w - __high2float(h1);
    hi[i * 2]     = h0;
    hi[i * 2 + 1] = h1;
    lo[i * 2]     = __floats2bfloat162_rn(rx, ry);
    lo[i * 2 + 1] = __floats2bfloat162_rn(rz, rw);
}

// ===========================================================================
// Tensor-core GEMM:  C[M,N] = A[M,K](fp32) @ Wt[N,K](bf16 hi/lo)  (+bias,+relu)
// 3-pass hi/lo split, fp32 accum. 128x128 CTA, BK=64, 8 warps (2x4), 64x32 warp.
// B via cp.async (pre-converted bf16); A LDG+split+STS. Double-buffered smem.
// ===========================================================================
#define PITCH 72                          // bf16 elems per smem row (64 used)
#define TILEB (128 * PITCH * 2)           // 18432 B
#define STAGEB (4 * TILEB)                // 73728 B  (Ahi, Alo, Bhi, Blo)
#define GEMM_SMEM (2 * STAGEB)            // 147456 B

template <bool BIAS, bool RELU>
__global__ void __launch_bounds__(256, 1)
tc_gemm(const float* __restrict__ A,
        const __nv_bfloat16* __restrict__ Bhi_g,
        const __nv_bfloat16* __restrict__ Blo_g,
        const float* __restrict__ bias, float* __restrict__ C,
        int M, int N, int K)
{
    extern __shared__ char smem[];
    const int tid  = threadIdx.x;
    const int wid  = tid >> 5;
    const int lane = tid & 31;
    const int g    = lane >> 2;
    const int t    = lane & 3;
    const int wm   = wid & 1;
    const int wn   = wid >> 1;
    const int m0   = blockIdx.y * 128;
    const int n0   = blockIdx.x * 128;

    const int arow = tid >> 4;   // 0..15 (x8 iters -> 128 rows)
    const int ac4  = tid & 15;   // float4 index within 64-col row

    float4 aR[8];
    float acc[4][4][4];
#pragma unroll
    for (int i = 0; i < 4; i++)
#pragma unroll
        for (int j = 0; j < 4; j++)
#pragma unroll
            for (int c = 0; c < 4; c++) acc[i][j][c] = 0.f;

    const int S = K >> 6;

    auto ldgA = [&](int s) {
        const int k0 = s << 6;
#pragma unroll
        for (int i = 0; i < 8; i++) {
            int row = arow + i * 16;
            aR[i] = *reinterpret_cast<const float4*>(
                A + (size_t)(m0 + row) * K + k0 + ac4 * 4);
        }
    };

    auto stsA = [&](int b) {
        char* Ahi = smem + b * STAGEB;
        char* Alo = Ahi + TILEB;
#pragma unroll
        for (int i = 0; i < 8; i++) {
            int row = arow + i * 16;
            uint32_t h0, l0, h1, l1;
            split2(aR[i].x, aR[i].y, h0, l0);
            split2(aR[i].z, aR[i].w, h1, l1);
            uint32_t byte = (uint32_t)(row * (PITCH * 2) + ac4 * 8);
            *reinterpret_cast<uint64_t*>(Ahi + byte) = ((uint64_t)h1 << 32) | h0;
            *reinterpret_cast<uint64_t*>(Alo + byte) = ((uint64_t)l1 << 32) | l0;
        }
    };

    auto cpB = [&](int s, int b) {
        const int k0 = s << 6;
        char* Bhi_s = smem + b * STAGEB + 2 * TILEB;
        char* Blo_s = smem + b * STAGEB + 3 * TILEB;
#pragma unroll
        for (int i = 0; i < 8; i++) {
            int idx  = tid + i * 256;          // 0..2047
            int r    = (idx & 1023) >> 3;      // 0..127
            int c16  = idx & 7;                // 16B unit
            uint32_t dst;
            const __nv_bfloat16* src;
            if (i < 4) {
                src = Bhi_g + (size_t)(n0 + r) * K + k0 + c16 * 8;
                dst = smem_u32(Bhi_s + r * (PITCH * 2) + c16 * 16);
            } else {
                src = Blo_g + (size_t)(n0 + r) * K + k0 + c16 * 8;
                dst = smem_u32(Blo_s + r * (PITCH * 2) + c16 * 16);
            }
            CP_ASYNC16(dst, src);
        }
    };

    auto compute = [&](int b) {
        const __nv_bfloat16* Ah = reinterpret_cast<const __nv_bfloat16*>(smem + b * STAGEB);
        const __nv_bfloat16* Al = Ah + 128 * PITCH;
        const __nv_bfloat16* Bh = Al + 128 * PITCH;
        const __nv_bfloat16* Bl = Bh + 128 * PITCH;
#pragma unroll
        for (int ks = 0; ks < 4; ks++) {
            const int kb = ks * 16 + t * 2;
            uint32_t ah[4][4], al[4][4], bh[4][2], bl[4][2];
#pragma unroll
            for (int mt = 0; mt < 4; mt++) {
                const __nv_bfloat16* p = Ah + (wm * 64 + mt * 16 + g) * PITCH + kb;
                ah[mt][0] = *reinterpret_cast<const uint32_t*>(p);
                ah[mt][1] = *reinterpret_cast<const uint32_t*>(p + 8 * PITCH);
                ah[mt][2] = *reinterpret_cast<const uint32_t*>(p + 8);
                ah[mt][3] = *reinterpret_cast<const uint32_t*>(p + 8 * PITCH + 8);
            }
#pragma unroll
            for (int nt = 0; nt < 4; nt++) {
                const __nv_bfloat16* p = Bh + (wn * 32 + nt * 8 + g) * PITCH + kb;
                bh[nt][0] = *reinterpret_cast<const uint32_t*>(p);
                bh[nt][1] = *reinterpret_cast<const uint32_t*>(p + 8);
            }
#pragma unroll
            for (int mt = 0; mt < 4; mt++)
#pragma unroll
                for (int nt = 0; nt < 4; nt++)
                    mma_bf16(acc[mt][nt], ah[mt], bh[nt]);
#pragma unroll
            for (int nt = 0; nt < 4; nt++) {
                const __nv_bfloat16* p = Bl + (wn * 32 + nt * 8 + g) * PITCH + kb;
                bl[nt][0] = *reinterpret_cast<const uint32_t*>(p);
                bl[nt][1] = *reinterpret_cast<const uint32_t*>(p + 8);
            }
#pragma unroll
            for (int mt = 0; mt < 4; mt++)
#pragma unroll
                for (int nt = 0; nt < 4; nt++)
                    mma_bf16(acc[mt][nt], ah[mt], bl[nt]);
#pragma unroll
            for (int mt = 0; mt < 4; mt++) {
                const __nv_bfloat16* p = Al + (wm * 64 + mt * 16 + g) * PITCH + kb;
                al[mt][0] = *reinterpret_cast<const uint32_t*>(p);
                al[mt][1] = *reinterpret_cast<const uint32_t*>(p + 8 * PITCH);
                al[mt][2] = *reinterpret_cast<const uint32_t*>(p + 8);
                al[mt][3] = *reinterpret_cast<const uint32_t*>(p + 8 * PITCH + 8);
            }
#pragma unroll
            for (int mt = 0; mt < 4; mt++)
#pragma unroll
                for (int nt = 0; nt < 4; nt++)
                    mma_bf16(acc[mt][nt], al[mt], bh[nt]);
        }
    };

    // ---- pipeline ----
    ldgA(0);
    cpB(0, 0);
    CP_COMMIT();
    stsA(0);
    CP_WAIT0();
    __syncthreads();

    for (int s = 0; s < S; s++) {
        const int b = s & 1;
        if (s + 1 < S) { ldgA(s + 1); cpB(s + 1, b ^ 1); CP_COMMIT(); }
        compute(b);
        if (s + 1 < S) stsA(b ^ 1);
        CP_WAIT0();
        __syncthreads();
    }

    // ---- epilogue: regs -> smem stage -> coalesced global (+bias/relu) ----
    float* stage = reinterpret_cast<float*>(smem);   // 128 x pitch 132
#pragma unroll
    for (int mt = 0; mt < 4; mt++) {
#pragma unroll
        for (int nt = 0; nt < 4; nt++) {
            int row = wm * 64 + mt * 16 + g;
            int col = wn * 32 + nt * 8 + t * 2;
            *reinterpret_cast<float2*>(&stage[row * 132 + col]) =
                make_float2(acc[mt][nt][0], acc[mt][nt][1]);
            *reinterpret_cast<float2*>(&stage[(row + 8) * 132 + col]) =
                make_float2(acc[mt][nt][2], acc[mt][nt][3]);
        }
    }
    __syncthreads();

#pragma unroll
    for (int i = 0; i < 16; i++) {
        int f   = i * 256 + tid;
        int row = f >> 5;
        int c4  = f & 31;
        float4 v = *reinterpret_cast<float4*>(&stage[row * 132 + c4 * 4]);
        if (BIAS) {
            float4 bv = *reinterpret_cast<const float4*>(bias + n0 + c4 * 4);
            v.x += bv.x; v.y += bv.y; v.z += bv.z; v.w += bv.w;
        }
        if (RELU) {
            v.x = fmaxf(v.x, 0.f); v.y = fmaxf(v.y, 0.f);
            v.z = fmaxf(v.z, 0.f); v.w = fmaxf(v.w, 0.f);
        }
        *reinterpret_cast<float4*>(C + (size_t)(m0 + row) * N + n0 + c4 * 4) = v;
    }
}

// ---------------------------------------------------------------------------
// Fused attention (flash-style online softmax), fp32, vectorized LDS + __expf
// ---------------------------------------------------------------------------
template <bool CAUSAL>
__global__ void __launch_bounds__(128)
attn_kernel(const float* __restrict__ Q, const float* __restrict__ K,
            const float* __restrict__ V, float* __restrict__ O, int Lk)
{
    __shared__ float Qs[32 * 64];
    __shared__ float Kst[64 * 33];
    __shared__ float Vs[32 * 68];
    __shared__ float Ps[32 * 32];

    const int b    = blockIdx.z;
    const int h    = blockIdx.y;
    const int q0   = blockIdx.x * 32;
    const int tid  = threadIdx.x;
    const int lane = tid & 31;
    const int w    = tid >> 5;
    const int r0   = w * 8;

#pragma unroll
    for (int s = tid; s < 512; s += 128) {
        int r  = s >> 4;
        int c4 = s & 15;
        float4 v = *reinterpret_cast<const float4*>(
            Q + (size_t)(b * Sc + q0 + r) * Dc + h * 64 + c4 * 4);
        *reinterpret_cast<float4*>(&Qs[r * 64 + c4 * 4]) = v;
    }

    float m_run[8], l_run[8], o0[8], o1[8];
#pragma unroll
    for (int r = 0; r < 8; r++) { m_run[r] = -1e30f; l_run[r] = 0.f; o0[r] = 0.f; o1[r] = 0.f; }

    const int nkt = CAUSAL ? (blockIdx.x + 1) : (Lk >> 5);

    for (int kt = 0; kt < nkt; kt++) {
        const int k0 = kt * 32;
        __syncthreads();
#pragma unroll
        for (int s = tid; s < 512; s += 128) {
            int r  = s >> 4;
            int c4 = s & 15;
            size_t base = (size_t)(b * Lk + k0 + r) * Dc + h * 64 + c4 * 4;
            float4 kv = *reinterpret_cast<const float4*>(K + base);
            Kst[(c4 * 4 + 0) * 33 + r] = kv.x;
            Kst[(c4 * 4 + 1) * 33 + r] = kv.y;
            Kst[(c4 * 4 + 2) * 33 + r] = kv.z;
            Kst[(c4 * 4 + 3) * 33 + r] = kv.w;
            float4 vv = *reinterpret_cast<const float4*>(V + base);
            *reinterpret_cast<float4*>(&Vs[r * 68 + c4 * 4]) = vv;
        }
        __syncthreads();

        // ---- scores: lane owns key k0+lane; vectorized Q reads ----
        float sc[8];
#pragma unroll
        for (int r = 0; r < 8; r++) sc[r] = 0.f;
#pragma unroll
        for (int d4 = 0; d4 < 16; d4++) {
            float k0v = Kst[(d4 * 4 + 0) * 33 + lane];
            float k1v = Kst[(d4 * 4 + 1) * 33 + lane];
            float k2v = Kst[(d4 * 4 + 2) * 33 + lane];
            float k3v = Kst[(d4 * 4 + 3) * 33 + lane];
#pragma unroll
            for (int r = 0; r < 8; r++) {
                float4 qv = *reinterpret_cast<const float4*>(&Qs[(r0 + r) * 64 + d4 * 4]);
                sc[r] += qv.x * k0v + qv.y * k1v + qv.z * k2v + qv.w * k3v;
            }
        }
#pragma unroll
        for (int r = 0; r < 8; r++) {
            sc[r] *= 0.125f;
            if (CAUSAL) {
                int qg = q0 + r0 + r;
                int kg = k0 + lane;
                if (kg > qg) sc[r] = -1e9f;
            }
        }
        // ---- online softmax ----
#pragma unroll
        for (int r = 0; r < 8; r++) {
            float mx = sc[r];
#pragma unroll
            for (int off = 16; off > 0; off >>= 1)
                mx = fmaxf(mx, __shfl_xor_sync(0xffffffffu, mx, off));
            float m_new = fmaxf(m_run[r], mx);
            float p = __expf(sc[r] - m_new);
            float ps = p;
#pragma unroll
            for (int off = 16; off > 0; off >>= 1)
                ps += __shfl_xor_sync(0xffffffffu, ps, off);
            float alpha = __expf(m_run[r] - m_new);
            l_run[r] = l_run[r] * alpha + ps;
            m_run[r] = m_new;
            o0[r] *= alpha;
            o1[r] *= alpha;
            Ps[(r0 + r) * 32 + lane] = p;
        }
        __syncwarp();
        // ---- PV: vectorized P reads ----
#pragma unroll
        for (int k4 = 0; k4 < 8; k4++) {
            float v00 = Vs[(k4 * 4 + 0) * 68 + lane];
            float v01 = Vs[(k4 * 4 + 1) * 68 + lane];
            float v02 = Vs[(k4 * 4 + 2) * 68 + lane];
            float v03 = Vs[(k4 * 4 + 3) * 68 + lane];
            float v10 = Vs[(k4 * 4 + 0) * 68 + 32 + lane];
            float v11 = Vs[(k4 * 4 + 1) * 68 + 32 + lane];
            float v12 = Vs[(k4 * 4 + 2) * 68 + 32 + lane];
            float v13 = Vs[(k4 * 4 + 3) * 68 + 32 + lane];
#pragma unroll
            for (int r = 0; r < 8; r++) {
                float4 pv = *reinterpret_cast<const float4*>(&Ps[(r0 + r) * 32 + k4 * 4]);
                o0[r] += pv.x * v00 + pv.y * v01 + pv.z * v02 + pv.w * v03;
                o1[r] += pv.x * v10 + pv.y * v11 + pv.z * v12 + pv.w * v13;
            }
        }
    }

#pragma unroll
    for (int r = 0; r < 8; r++) {
        float invl = 1.f / l_run[r];
        float* op = O + (size_t)(b * Sc + q0 + r0 + r) * Dc + h * 64;
        op[lane]      = o0[r] * invl;
        op[32 + lane] = o1[r] * invl;
    }
}

// ---------------------------------------------------------------------------
// Residual + LayerNorm
// ---------------------------------------------------------------------------
__global__ void __launch_bounds__(256)
ln_kernel(const float* __restrict__ x, const float* __restrict__ add,
          const float* __restrict__ s, const float* __restrict__ b,
          float* __restrict__ out)
{
    const int row = blockIdx.x;
    const int tid = threadIdx.x;
    const size_t base = (size_t)row * Dc;

    float v[4];
    float sum = 0.f, sq = 0.f;
#pragma unroll
    for (int i = 0; i < 4; i++) {
        int c = tid + i * 256;
        float val = x[base + c];
        if (add) val += add[base + c];
        v[i] = val;
        sum += val;
        sq  += val * val;
    }
#pragma unroll
    for (int off = 16; off > 0; off >>= 1) {
        sum += __shfl_xor_sync(0xffffffffu, sum, off);
        sq  += __shfl_xor_sync(0xffffffffu, sq, off);
    }
    __shared__ float s1[8], s2[8];
    __shared__ float mu_s, inv_s;
    int lane = tid & 31, wid = tid >> 5;
    if (lane == 0) { s1[wid] = sum; s2[wid] = sq; }
    __syncthreads();
    if (tid == 0) {
        float ts = 0.f, tq = 0.f;
#pragma unroll
        for (int i = 0; i < 8; i++) { ts += s1[i]; tq += s2[i]; }
        float mu  = ts * (1.f / Dc);
        float var = tq * (1.f / Dc) - mu * mu;
        mu_s  = mu;
        inv_s = rsqrtf(var + 1e-5f);
    }
    __syncthreads();
    float mu = mu_s, inv = inv_s;
#pragma unroll
    for (int i = 0; i < 4; i++) {
        int c = tid + i * 256;
        out[base + c] = (v[i] - mu) * inv * s[c] + b[c];
    }
}

// ---------------------------------------------------------------------------
// Embedding gather + positional add
// ---------------------------------------------------------------------------
__global__ void __launch_bounds__(256)
embed_kernel(const int* __restrict__ seq, const float* __restrict__ emb,
             const float* __restrict__ pos, float* __restrict__ x)
{
    const int row  = blockIdx.x;
    const int sidx = row & (Sc - 1);
    const int tok  = seq[row];
    const int tid  = threadIdx.x;
#pragma unroll
    for (int i = 0; i < 4; i++) {
        int c = tid + i * 256;
        x[(size_t)row * Dc + c] = emb[(size_t)tok * Dc + c] + pos[(size_t)sidx * Dc + c];
    }
}

// ---------------------------------------------------------------------------
// Host orchestration
// ---------------------------------------------------------------------------
template <bool BIAS, bool RELU>
static void launch_gemm(const float* A, const __nv_bfloat16* bhi, const __nv_bfloat16* blo,
                        const float* bias, float* C, int M, int N, int K)
{
    cudaFuncSetAttribute(tc_gemm<BIAS, RELU>,
                         cudaFuncAttributeMaxDynamicSharedMemorySize, GEMM_SMEM);
    dim3 grid(N / 128, M / 128);
    tc_gemm<BIAS, RELU><<<grid, 256, GEMM_SMEM>>>(A, bhi, blo, bias, C, M, N, K);
}

extern "C" void kernel_launch(void* const* d_in, const int* in_sizes, int n_in,
                              void* d_out, int out_size)
{
    (void)in_sizes; (void)n_in; (void)out_size;

    const float* encoded      = (const float*)d_in[0];
    const int*   seq          = (const int*)  d_in[1];
    const float* input_embed  = (const float*)d_in[2];
    const float* output_embed = (const float*)d_in[3];
    const float* output_bias  = (const float*)d_in[4];
    const float* pos_embed    = (const float*)d_in[5];
    const float* Wq  = (const float*)d_in[6];
    const float* Wk  = (const float*)d_in[7];
    const float* Wv  = (const float*)d_in[8];
    const float* Wo  = (const float*)d_in[9];
    const float* Wqc = (const float*)d_in[10];
    const float* Wkc = (const float*)d_in[11];
    const float* Wvc = (const float*)d_in[12];
    const float* Woc = (const float*)d_in[13];
    const float* W1  = (const float*)d_in[14];
    const float* b1  = (const float*)d_in[15];
    const float* W2  = (const float*)d_in[16];
    const float* b2  = (const float*)d_in[17];
    const float* ln1s = (const float*)d_in[18];
    const float* ln1b = (const float*)d_in[19];
    const float* ln2s = (const float*)d_in[20];
    const float* ln2b = (const float*)d_in[21];
    const float* ln3s = (const float*)d_in[22];
    const float* ln3b = (const float*)d_in[23];
    const float* lnfs = (const float*)d_in[24];
    const float* lnfb = (const float*)d_in[25];

    float *x, *q, *k, *v, *a, *o, *f;
    cudaGetSymbolAddress((void**)&x, g_x);
    cudaGetSymbolAddress((void**)&q, g_q);
    cudaGetSymbolAddress((void**)&k, g_k);
    cudaGetSymbolAddress((void**)&v, g_v);
    cudaGetSymbolAddress((void**)&a, g_a);
    cudaGetSymbolAddress((void**)&o, g_o);
    cudaGetSymbolAddress((void**)&f, g_f);
    __nv_bfloat16 *whi, *wlo;
    cudaGetSymbolAddress((void**)&whi, g_whi);
    cudaGetSymbolAddress((void**)&wlo, g_wlo);

    // ---- weight conversion (graph nodes; run each replay) ----
    {
        const dim3 tb(32, 8);
        const dim3 gSq(32, 32);     // 1024x1024
        for (int i = 0; i < Lc; i++) {
            const size_t wo  = (size_t)i * Dc * Dc;
            const size_t lb  = (size_t)i * WOFF_LAYER;
            const float* ws[8] = { Wq + wo, Wk + wo, Wv + wo, Wo + wo,
                                   Wqc + wo, Wkc + wo, Wvc + wo, Woc + wo };
            for (int j = 0; j < 8; j++)
                convT_kernel<<<gSq, tb>>>(ws[j], whi + lb + (size_t)j * 1048576,
                                          wlo + lb + (size_t)j * 1048576, Dc, Dc);
            // W1 [1024,4096] -> [4096,1024]
            convT_kernel<<<dim3(DFc / 32, Dc / 32), tb>>>(
                W1 + (size_t)i * Dc * DFc, whi + lb + WOFF_W1, wlo + lb + WOFF_W1, Dc, DFc);
            // W2 [4096,1024] -> [1024,4096]
            convT_kernel<<<dim3(Dc / 32, DFc / 32), tb>>>(
                W2 + (size_t)i * DFc * Dc, whi + lb + WOFF_W2, wlo + lb + WOFF_W2, DFc, Dc);
        }
        // output_embed [32000,1024] (already [N,K])
        conv_kernel<<<Vc, 256>>>((const float4*)output_embed,
                                 (__nv_bfloat162*)(whi + EOFF),
                                 (__nv_bfloat162*)(wlo + EOFF));
    }

    const int NR  = Bc * Sc;   // 4096
    const int NRE = Bc * Mc;   // 8192

    embed_kernel<<<NR, 256>>>(seq, input_embed, pos_embed, x);

    const dim3 agrid(Sc / 32, Hc, Bc);   // (16, 16, 8)

    for (int i = 0; i < Lc; i++) {
        const size_t lb = (size_t)i * WOFF_LAYER;
        const __nv_bfloat16* wq  = whi + lb;
        const __nv_bfloat16* lq  = wlo + lb;

        // ---- self attention ----
        launch_gemm<false, false>(x, wq + 0 * 1048576, lq + 0 * 1048576, nullptr, q, NR, Dc, Dc);
        launch_gemm<false, false>(x, wq + 1 * 1048576, lq + 1 * 1048576, nullptr, k, NR, Dc, Dc);
        launch_gemm<false, false>(x, wq + 2 * 1048576, lq + 2 * 1048576, nullptr, v, NR, Dc, Dc);
        attn_kernel<true><<<agrid, 128>>>(q, k, v, a, Sc);
        launch_gemm<false, false>(a, wq + 3 * 1048576, lq + 3 * 1048576, nullptr, o, NR, Dc, Dc);
        ln_kernel<<<NR, 256>>>(x, o, ln1s + (size_t)i * Dc, ln1b + (size_t)i * Dc, x);

        // ---- cross attention ----
        launch_gemm<false, false>(x,       wq + 4 * 1048576, lq + 4 * 1048576, nullptr, q, NR,  Dc, Dc);
        launch_gemm<false, false>(encoded, wq + 5 * 1048576, lq + 5 * 1048576, nullptr, k, NRE, Dc, Dc);
        launch_gemm<false, false>(encoded, wq + 6 * 1048576, lq + 6 * 1048576, nullptr, v, NRE, Dc, Dc);
        attn_kernel<false><<<agrid, 128>>>(q, k, v, a, Mc);
        launch_gemm<false, false>(a, wq + 7 * 1048576, lq + 7 * 1048576, nullptr, o, NR, Dc, Dc);
        ln_kernel<<<NR, 256>>>(x, o, ln2s + (size_t)i * Dc, ln2b + (size_t)i * Dc, x);

        // ---- FFN ----
        launch_gemm<true, true >(x, wq + WOFF_W1, lq + WOFF_W1, b1 + (size_t)i * DFc,
                                 f, NR, DFc, Dc);
        launch_gemm<true, false>(f, wq + WOFF_W2, lq + WOFF_W2, b2 + (size_t)i * Dc,
                                 o, NR, Dc, DFc);
        ln_kernel<<<NR, 256>>>(x, o, ln3s + (size_t)i * Dc, ln3b + (size_t)i * Dc, x);
    }

    // final norm + logits: out = LN(x) @ E^T + bias
    ln_kernel<<<NR, 256>>>(x, nullptr, lnfs, lnfb, x);
    launch_gemm<true, false>(x, whi + EOFF, wlo + EOFF, output_bias, (float*)d_out, NR, Vc, Dc);
}